// round 3
// baseline (speedup 1.0000x reference)
#include <cuda_runtime.h>
#include <math.h>
#include <stdint.h>

// Problem constants
#define Bsz 2
#define Sq  2048
#define DM  2048
#define Hh  16
#define DQKd 128
#define DVd  85
#define DVH  1360            // DVd * Hh
#define NV   2720            // DVH * 2
#define BS   (Bsz * Sq)      // 4096
#define ATT_SCALE 0.08838834764831843f   // 1/sqrt(128)

// ---------------------------------------------------------------------------
// Scratch (no cudaMalloc allowed -> __device__ globals)
// ---------------------------------------------------------------------------
__device__ float g_qp[(size_t)BS * DM];                 // 33.5 MB
__device__ float g_kp[(size_t)BS * DM];                 // 33.5 MB
__device__ float g_vp[(size_t)BS * NV];                 // 44.6 MB
__device__ float g_vg[(size_t)BS * DVH];                // 22.3 MB
__device__ float g_oc[(size_t)BS * DVH];                // 22.3 MB
__device__ float g_sc[(size_t)Bsz * Hh * Sq * Sq];      // 536 MB

// ---------------------------------------------------------------------------
// tf32 helpers
// ---------------------------------------------------------------------------
__device__ __forceinline__ uint32_t f2tf32(float x) {
    uint32_t r;
    asm("cvt.rna.tf32.f32 %0, %1;" : "=r"(r) : "f"(x));
    return r;
}

#define MMA_TF32(D, A, B)                                               \
    asm volatile(                                                       \
        "mma.sync.aligned.m16n8k8.row.col.f32.tf32.tf32.f32 "           \
        "{%0,%1,%2,%3}, {%4,%5,%6,%7}, {%8,%9}, {%0,%1,%2,%3};"         \
        : "+f"((D)[0]), "+f"((D)[1]), "+f"((D)[2]), "+f"((D)[3])        \
        : "r"((A)[0]), "r"((A)[1]), "r"((A)[2]), "r"((A)[3]),           \
          "r"((B)[0]), "r"((B)[1]))

// Split x into hi(tf32) + lo(tf32)
#define SPLIT_TF32(hi, lo, x)                                           \
    do { (hi) = f2tf32(x); (lo) = f2tf32((x) - __uint_as_float(hi)); } while (0)

// ---------------------------------------------------------------------------
// 3xTF32 tensor-core GEMM: C[M,N] = A[M,K] @ W[K,N] + bias[N]
// 128x128 block tile, BK=16, 256 threads (8 warps, 2x4), warp tile 64x32.
// Error ~eps_tf32^2 ~ 2e-7.  M % 128 == 0, K % 16 == 0; N guarded.
// ---------------------------------------------------------------------------
__global__ __launch_bounds__(256) void sgemm_tf32_kernel(
    const float* __restrict__ A, const float* __restrict__ W,
    const float* __restrict__ bias, float* __restrict__ C,
    int M, int N, int K)
{
    __shared__ float As[16][132];   // [k][m]
    __shared__ float Ws[16][132];   // [k][n]

    const int tid  = threadIdx.x;
    const int warp = tid >> 5;
    const int lane = tid & 31;
    const int gid  = lane >> 2;
    const int tig  = lane & 3;
    const int warp_m = (warp & 1) * 64;
    const int warp_n = (warp >> 1) * 32;
    const int mBase = blockIdx.y * 128;
    const int nBase = blockIdx.x * 128;

    float acc[4][4][4];
#pragma unroll
    for (int mf = 0; mf < 4; mf++)
#pragma unroll
        for (int nf = 0; nf < 4; nf++)
#pragma unroll
            for (int r = 0; r < 4; r++) acc[mf][nf][r] = 0.f;

    const int nkt = K >> 4;
    for (int kt = 0; kt < nkt; kt++) {
#pragma unroll
        for (int t = 0; t < 2; t++) {
            int idx = tid + (t << 8);
            int row = idx >> 2;
            int c4  = (idx & 3) << 2;
            float4 v = *(const float4*)(A + (size_t)(mBase + row) * K + (kt << 4) + c4);
            As[c4 + 0][row] = v.x; As[c4 + 1][row] = v.y;
            As[c4 + 2][row] = v.z; As[c4 + 3][row] = v.w;
        }
#pragma unroll
        for (int t = 0; t < 2; t++) {
            int idx = tid + (t << 8);
            int r   = idx >> 5;
            int c   = (idx & 31) << 2;
            int col = nBase + c;
            float4 v = make_float4(0.f, 0.f, 0.f, 0.f);
            if (col < N) v = *(const float4*)(W + (size_t)((kt << 4) + r) * N + col);
            Ws[r][c + 0] = v.x; Ws[r][c + 1] = v.y;
            Ws[r][c + 2] = v.z; Ws[r][c + 3] = v.w;
        }
        __syncthreads();

#pragma unroll
        for (int ks = 0; ks < 2; ks++) {
            const int kb = ks << 3;
            uint32_t ahi[4][4], alo[4][4];
#pragma unroll
            for (int mf = 0; mf < 4; mf++) {
                int m0 = warp_m + (mf << 4) + gid;
                SPLIT_TF32(ahi[mf][0], alo[mf][0], As[kb + tig    ][m0]);
                SPLIT_TF32(ahi[mf][1], alo[mf][1], As[kb + tig    ][m0 + 8]);
                SPLIT_TF32(ahi[mf][2], alo[mf][2], As[kb + tig + 4][m0]);
                SPLIT_TF32(ahi[mf][3], alo[mf][3], As[kb + tig + 4][m0 + 8]);
            }
            uint32_t bhi[4][2], blo[4][2];
#pragma unroll
            for (int nf = 0; nf < 4; nf++) {
                int n0 = warp_n + (nf << 3) + gid;
                SPLIT_TF32(bhi[nf][0], blo[nf][0], Ws[kb + tig    ][n0]);
                SPLIT_TF32(bhi[nf][1], blo[nf][1], Ws[kb + tig + 4][n0]);
            }
#pragma unroll
            for (int mf = 0; mf < 4; mf++)
#pragma unroll
                for (int nf = 0; nf < 4; nf++) {
                    MMA_TF32(acc[mf][nf], ahi[mf], bhi[nf]);
                    MMA_TF32(acc[mf][nf], ahi[mf], blo[nf]);
                    MMA_TF32(acc[mf][nf], alo[mf], bhi[nf]);
                }
        }
        __syncthreads();
    }

#pragma unroll
    for (int mf = 0; mf < 4; mf++) {
#pragma unroll
        for (int nf = 0; nf < 4; nf++) {
            int row0 = mBase + warp_m + (mf << 4) + gid;
            int col0 = nBase + warp_n + (nf << 3) + (tig << 1);
            if (col0 < N) {
                float b0 = bias[col0], b1 = bias[col0 + 1];
                C[(size_t)row0 * N + col0]           = acc[mf][nf][0] + b0;
                C[(size_t)row0 * N + col0 + 1]       = acc[mf][nf][1] + b1;
                C[(size_t)(row0 + 8) * N + col0]     = acc[mf][nf][2] + b0;
                C[(size_t)(row0 + 8) * N + col0 + 1] = acc[mf][nf][3] + b1;
            }
        }
    }
}

// ---------------------------------------------------------------------------
// SiLU gate: vg[m,j] = vp[m,j] * silu(vp[m,j+DVH])
// ---------------------------------------------------------------------------
__global__ void gate_kernel(const float* __restrict__ vp, float* __restrict__ vg)
{
    int idx = blockIdx.x * blockDim.x + threadIdx.x;
    if (idx >= BS * DVH) return;
    int m = idx / DVH, j = idx - m * DVH;
    float a = vp[(size_t)m * NV + j];
    float g = vp[(size_t)m * NV + DVH + j];
    vg[idx] = a * (g / (1.f + __expf(-g)));
}

// ---------------------------------------------------------------------------
// RoPE in place on [BS, H, 128]; pairs (d, d+64) within each head.
// ---------------------------------------------------------------------------
__global__ void rope_kernel(float* __restrict__ x)
{
    int idx = blockIdx.x * blockDim.x + threadIdx.x;
    if (idx >= BS * Hh * 64) return;
    int d  = idx & 63;
    int h  = (idx >> 6) & 15;
    int bs = idx >> 10;
    int s  = bs & (Sq - 1);
    float invf = powf(10000.f, -(float)d * (1.f / 64.f));
    float ang  = (float)s * invf;
    float c, sn;
    sincosf(ang, &sn, &c);
    size_t base = (size_t)bs * DM + (size_t)h * DQKd + d;
    float x1 = x[base], x2 = x[base + 64];
    x[base]      = x1 * c - x2 * sn;
    x[base + 64] = x2 * c + x1 * sn;
}

// ---------------------------------------------------------------------------
// Scores via 3xTF32 tensor cores: sc[z,i,j] = SCALE * sum_d Q[z,i,d] K[z,j,d]
// 128x128 tile, BK=16, K-dim=128. Skips fully-masked tiles.
// Both Q and K tiles are K-contiguous rows with stride DM.
// ---------------------------------------------------------------------------
__global__ __launch_bounds__(256) void score_tf32_kernel(
    const float* __restrict__ qp, const float* __restrict__ kp,
    float* __restrict__ sc)
{
    const int iBase = blockIdx.y * 128;
    const int jBase = blockIdx.x * 128;
    if (jBase > iBase + 127) return;
    const int z = blockIdx.z;
    const int b = z >> 4, h = z & 15;
    const size_t hbase = ((size_t)b * Sq) * DM + (size_t)h * DQKd;
    const float* Q  = qp + hbase;
    const float* Km = kp + hbase;

    __shared__ float Qs[16][132];   // [k][i]
    __shared__ float Ks[16][132];   // [k][j]

    const int tid  = threadIdx.x;
    const int warp = tid >> 5;
    const int lane = tid & 31;
    const int gid  = lane >> 2;
    const int tig  = lane & 3;
    const int warp_m = (warp & 1) * 64;
    const int warp_n = (warp >> 1) * 32;

    float acc[4][4][4];
#pragma unroll
    for (int mf = 0; mf < 4; mf++)
#pragma unroll
        for (int nf = 0; nf < 4; nf++)
#pragma unroll
            for (int r = 0; r < 4; r++) acc[mf][nf][r] = 0.f;

#pragma unroll
    for (int kt = 0; kt < 8; kt++) {    // DQK/16
#pragma unroll
        for (int t = 0; t < 2; t++) {
            int idx = tid + (t << 8);
            int row = idx >> 2;
            int c4  = (idx & 3) << 2;
            float4 v = *(const float4*)(Q + (size_t)(iBase + row) * DM + (kt << 4) + c4);
            Qs[c4 + 0][row] = v.x; Qs[c4 + 1][row] = v.y;
            Qs[c4 + 2][row] = v.z; Qs[c4 + 3][row] = v.w;
        }
#pragma unroll
        for (int t = 0; t < 2; t++) {
            int idx = tid + (t << 8);
            int row = idx >> 2;
            int c4  = (idx & 3) << 2;
            float4 v = *(const float4*)(Km + (size_t)(jBase + row) * DM + (kt << 4) + c4);
            Ks[c4 + 0][row] = v.x; Ks[c4 + 1][row] = v.y;
            Ks[c4 + 2][row] = v.z; Ks[c4 + 3][row] = v.w;
        }
        __syncthreads();

#pragma unroll
        for (int ks = 0; ks < 2; ks++) {
            const int kb = ks << 3;
            uint32_t ahi[4][4], alo[4][4];
#pragma unroll
            for (int mf = 0; mf < 4; mf++) {
                int m0 = warp_m + (mf << 4) + gid;
                SPLIT_TF32(ahi[mf][0], alo[mf][0], Qs[kb + tig    ][m0]);
                SPLIT_TF32(ahi[mf][1], alo[mf][1], Qs[kb + tig    ][m0 + 8]);
                SPLIT_TF32(ahi[mf][2], alo[mf][2], Qs[kb + tig + 4][m0]);
                SPLIT_TF32(ahi[mf][3], alo[mf][3], Qs[kb + tig + 4][m0 + 8]);
            }
            uint32_t bhi[4][2], blo[4][2];
#pragma unroll
            for (int nf = 0; nf < 4; nf++) {
                int n0 = warp_n + (nf << 3) + gid;
                SPLIT_TF32(bhi[nf][0], blo[nf][0], Ks[kb + tig    ][n0]);
                SPLIT_TF32(bhi[nf][1], blo[nf][1], Ks[kb + tig + 4][n0]);
            }
#pragma unroll
            for (int mf = 0; mf < 4; mf++)
#pragma unroll
                for (int nf = 0; nf < 4; nf++) {
                    MMA_TF32(acc[mf][nf], ahi[mf], bhi[nf]);
                    MMA_TF32(acc[mf][nf], ahi[mf], blo[nf]);
                    MMA_TF32(acc[mf][nf], alo[mf], bhi[nf]);
                }
        }
        __syncthreads();
    }

#pragma unroll
    for (int mf = 0; mf < 4; mf++) {
#pragma unroll
        for (int nf = 0; nf < 4; nf++) {
            int row0 = iBase + warp_m + (mf << 4) + gid;
            int col0 = jBase + warp_n + (nf << 3) + (tig << 1);
            size_t r0 = ((size_t)z * Sq + row0) * Sq;
            size_t r1 = ((size_t)z * Sq + row0 + 8) * Sq;
            sc[r0 + col0]     = acc[mf][nf][0] * ATT_SCALE;
            sc[r0 + col0 + 1] = acc[mf][nf][1] * ATT_SCALE;
            sc[r1 + col0]     = acc[mf][nf][2] * ATT_SCALE;
            sc[r1 + col0 + 1] = acc[mf][nf][3] * ATT_SCALE;
        }
    }
}

// ---------------------------------------------------------------------------
// Causal softmax per row. Zero-fills (i, next 128 boundary] so PV consumes
// whole 16-wide k-tiles up to that boundary.
// ---------------------------------------------------------------------------
__global__ __launch_bounds__(256) void softmax_kernel(float* __restrict__ sc)
{
    __shared__ float red[256];
    const int gid = blockIdx.x;          // z*Sq + i
    const int i   = gid & (Sq - 1);
    float* row = sc + (size_t)gid * Sq;
    const int L   = i + 1;
    const int tid = threadIdx.x;

    float m = -1e30f;
    for (int j = tid; j < L; j += 256) m = fmaxf(m, row[j]);
    red[tid] = m; __syncthreads();
    for (int s = 128; s > 0; s >>= 1) {
        if (tid < s) red[tid] = fmaxf(red[tid], red[tid + s]);
        __syncthreads();
    }
    m = red[0]; __syncthreads();

    float sum = 0.f;
    for (int j = tid; j < L; j += 256) sum += __expf(row[j] - m);
    red[tid] = sum; __syncthreads();
    for (int s = 128; s > 0; s >>= 1) {
        if (tid < s) red[tid] += red[tid + s];
        __syncthreads();
    }
    float inv = 1.f / red[0];

    for (int j = tid; j < L; j += 256) row[j] = __expf(row[j] - m) * inv;
    const int bound = ((i >> 7) + 1) << 7;
    for (int j = L + tid; j < bound; j += 256) row[j] = 0.f;
}

// ---------------------------------------------------------------------------
// O = P @ V via 3xTF32 tensor cores, per (b,h).
// Block tile: 128 rows x 96 cols (DV=85 zero-padded), BK=16.
// Warp layout 2x4 -> warp tile 64x24 (4 m-frags x 3 n-frags).
// k-tiles run only to the row-block's causal boundary (iBase+128).
// Writes compact concat layout oc[b, s, h*85 + dv].
// ---------------------------------------------------------------------------
__global__ __launch_bounds__(256) void pv_tf32_kernel(
    const float* __restrict__ sc, const float* __restrict__ vg,
    float* __restrict__ oc)
{
    const int z = blockIdx.z;
    const int b = z >> 4, h = z & 15;
    const int iBase = blockIdx.y * 128;

    __shared__ float Ps[16][132];    // [k][i]
    __shared__ float Vs[16][100];    // [k][dv] (96 + pad)

    const int tid  = threadIdx.x;
    const int warp = tid >> 5;
    const int lane = tid & 31;
    const int gid  = lane >> 2;
    const int tig  = lane & 3;
    const int warp_m = (warp & 1) * 64;
    const int warp_n = (warp >> 1) * 24;

    float acc[4][3][4];
#pragma unroll
    for (int mf = 0; mf < 4; mf++)
#pragma unroll
        for (int nf = 0; nf < 3; nf++)
#pragma unroll
            for (int r = 0; r < 4; r++) acc[mf][nf][r] = 0.f;

    const int nj = iBase + 128;              // causal limit (128-aligned)
    const size_t zrow = (size_t)z * Sq;
    const float* Vh = vg + (size_t)h * DVd;  // per-head V base

    for (int jt = 0; jt < nj; jt += 16) {
        // P tile 128x16 -> Ps[k][i]
#pragma unroll
        for (int t = 0; t < 2; t++) {
            int idx = tid + (t << 8);
            int row = idx >> 2;
            int c4  = (idx & 3) << 2;
            float4 v = *(const float4*)(sc + (zrow + iBase + row) * Sq + jt + c4);
            Ps[c4 + 0][row] = v.x; Ps[c4 + 1][row] = v.y;
            Ps[c4 + 2][row] = v.z; Ps[c4 + 3][row] = v.w;
        }
        // V tile 16x96 -> Vs[k][dv]  (zero-pad dv >= 85)
#pragma unroll
        for (int t = 0; t < 6; t++) {
            int idx = tid + (t << 8);   // 0..1535
            int kk  = idx / 96;
            int c   = idx - kk * 96;
            float val = 0.f;
            if (c < DVd)
                val = Vh[((size_t)(b * Sq + jt + kk)) * DVH + c];
            Vs[kk][c] = val;
        }
        __syncthreads();

#pragma unroll
        for (int ks = 0; ks < 2; ks++) {
            const int kb = ks << 3;
            uint32_t ahi[4][4], alo[4][4];
#pragma unroll
            for (int mf = 0; mf < 4; mf++) {
                int m0 = warp_m + (mf << 4) + gid;
                SPLIT_TF32(ahi[mf][0], alo[mf][0], Ps[kb + tig    ][m0]);
                SPLIT_TF32(ahi[mf][1], alo[mf][1], Ps[kb + tig    ][m0 + 8]);
                SPLIT_TF32(ahi[mf][2], alo[mf][2], Ps[kb + tig + 4][m0]);
                SPLIT_TF32(ahi[mf][3], alo[mf][3], Ps[kb + tig + 4][m0 + 8]);
            }
            uint32_t bhi[3][2], blo[3][2];
#pragma unroll
            for (int nf = 0; nf < 3; nf++) {
                int n0 = warp_n + (nf << 3) + gid;
                SPLIT_TF32(bhi[nf][0], blo[nf][0], Vs[kb + tig    ][n0]);
                SPLIT_TF32(bhi[nf][1], blo[nf][1], Vs[kb + tig + 4][n0]);
            }
#pragma unroll
            for (int mf = 0; mf < 4; mf++)
#pragma unroll
                for (int nf = 0; nf < 3; nf++) {
                    MMA_TF32(acc[mf][nf], ahi[mf], bhi[nf]);
                    MMA_TF32(acc[mf][nf], ahi[mf], blo[nf]);
                    MMA_TF32(acc[mf][nf], alo[mf], bhi[nf]);
                }
        }
        __syncthreads();
    }

    float* Oh = oc + (size_t)h * DVd;
#pragma unroll
    for (int mf = 0; mf < 4; mf++) {
#pragma unroll
        for (int nf = 0; nf < 3; nf++) {
            int row0 = iBase + warp_m + (mf << 4) + gid;
            int col0 = warp_n + (nf << 3) + (tig << 1);
            size_t r0 = ((size_t)(b * Sq + row0)) * DVH;
            size_t r1 = ((size_t)(b * Sq + row0 + 8)) * DVH;
            if (col0 < DVd)     Oh[r0 + col0]     = acc[mf][nf][0];
            if (col0 + 1 < DVd) Oh[r0 + col0 + 1] = acc[mf][nf][1];
            if (col0 < DVd)     Oh[r1 + col0]     = acc[mf][nf][2];
            if (col0 + 1 < DVd) Oh[r1 + col0 + 1] = acc[mf][nf][3];
        }
    }
}

// ---------------------------------------------------------------------------
// Launch
// Inputs: 0:q 1:k 2:v 3:mask(unused, causal is known) 4:Wq 5:bq 6:Wk 7:bk
//         8:Wv 9:bv 10:Wo 11:bo     Output: fp32 [B,S,DM]
// ---------------------------------------------------------------------------
extern "C" void kernel_launch(void* const* d_in, const int* in_sizes, int n_in,
                              void* d_out, int out_size)
{
    const float* q  = (const float*)d_in[0];
    const float* k  = (const float*)d_in[1];
    const float* v  = (const float*)d_in[2];
    const float* Wq = (const float*)d_in[4];
    const float* bq = (const float*)d_in[5];
    const float* Wk = (const float*)d_in[6];
    const float* bk = (const float*)d_in[7];
    const float* Wv = (const float*)d_in[8];
    const float* bv = (const float*)d_in[9];
    const float* Wo = (const float*)d_in[10];
    const float* bo = (const float*)d_in[11];
    float* out = (float*)d_out;

    float *qp, *kp, *vp, *vg, *oc, *sc;
    cudaGetSymbolAddress((void**)&qp, g_qp);
    cudaGetSymbolAddress((void**)&kp, g_kp);
    cudaGetSymbolAddress((void**)&vp, g_vp);
    cudaGetSymbolAddress((void**)&vg, g_vg);
    cudaGetSymbolAddress((void**)&oc, g_oc);
    cudaGetSymbolAddress((void**)&sc, g_sc);

    // Projections (3xTF32 tensor cores)
    sgemm_tf32_kernel<<<dim3(16, 32), 256>>>(q, Wq, bq, qp, BS, DM, DM);
    sgemm_tf32_kernel<<<dim3(16, 32), 256>>>(k, Wk, bk, kp, BS, DM, DM);
    sgemm_tf32_kernel<<<dim3(22, 32), 256>>>(v, Wv, bv, vp, BS, NV, DM);

    // SiLU gate on V
    gate_kernel<<<(BS * DVH + 255) / 256, 256>>>(vp, vg);

    // RoPE on Q and K (in place)
    rope_kernel<<<(BS * Hh * 64 + 255) / 256, 256>>>(qp);
    rope_kernel<<<(BS * Hh * 64 + 255) / 256, 256>>>(kp);

    // Attention (tensor cores)
    score_tf32_kernel<<<dim3(16, 16, 32), 256>>>(qp, kp, sc);
    softmax_kernel<<<Bsz * Hh * Sq, 256>>>(sc);
    pv_tf32_kernel<<<dim3(1, Sq / 128, Bsz * Hh), 256>>>(sc, vg, oc);

    // Output projection (3xTF32)
    sgemm_tf32_kernel<<<dim3(16, 32), 256>>>(oc, Wo, bo, out, BS, DM, DVH);
}

// round 8
// speedup vs baseline: 1.5763x; 1.5763x over previous
#include <cuda_runtime.h>
#include <cuda_bf16.h>
#include <math.h>
#include <stdint.h>

// Problem constants
#define Bsz 2
#define Sq  2048
#define DM  2048
#define Hh  16
#define DQKd 128
#define DVd  85
#define DVH  1360            // DVd * Hh
#define NV   2720            // DVH * 2
#define BS   (Bsz * Sq)      // 4096
#define ATT_SCALE 0.08838834764831843f   // 1/sqrt(128)

// ---------------------------------------------------------------------------
// Scratch (no cudaMalloc allowed -> __device__ globals)
// ---------------------------------------------------------------------------
__device__ float g_qp[(size_t)BS * DM];
__device__ float g_kp[(size_t)BS * DM];
__device__ float g_vp[(size_t)BS * NV];
__device__ float g_vg[(size_t)BS * DVH];
__device__ float g_oc[(size_t)BS * DVH];
__device__ float g_sc[(size_t)Bsz * Hh * Sq * Sq];

// ---------------------------------------------------------------------------
// bf16 split: x = hi + lo (both bf16); dropped lo*lo term ~2^-18.
// Split happens ONCE per element at the gmem->smem stage.
// ---------------------------------------------------------------------------
__device__ __forceinline__ void split2(float x0, float x1,
                                       uint32_t& hi, uint32_t& lo)
{
    __nv_bfloat16 h0 = __float2bfloat16_rn(x0);
    __nv_bfloat16 h1 = __float2bfloat16_rn(x1);
    __nv_bfloat16 l0 = __float2bfloat16_rn(x0 - __bfloat162float(h0));
    __nv_bfloat16 l1 = __float2bfloat16_rn(x1 - __bfloat162float(h1));
    hi = ((uint32_t)__bfloat16_as_ushort(h1) << 16) | __bfloat16_as_ushort(h0);
    lo = ((uint32_t)__bfloat16_as_ushort(l1) << 16) | __bfloat16_as_ushort(l0);
}

#define MMA_BF16(D, A, B0, B1)                                          \
    asm volatile(                                                       \
        "mma.sync.aligned.m16n8k16.row.col.f32.bf16.bf16.f32 "          \
        "{%0,%1,%2,%3}, {%4,%5,%6,%7}, {%8,%9}, {%0,%1,%2,%3};"         \
        : "+f"((D)[0]), "+f"((D)[1]), "+f"((D)[2]), "+f"((D)[3])        \
        : "r"((A)[0]), "r"((A)[1]), "r"((A)[2]), "r"((A)[3]),           \
          "r"(B0), "r"(B1))

// smem row stride in u32 (k-pair) units: 8 pairs (BK=16) + 4 pad -> 12
// Fragment-load bank check: addr = m*12 + tig; (gid,tig) covers all 32 banks.
#define SMB 12

// ---------------------------------------------------------------------------
// 3xBF16 tensor-core GEMM: C[M,N] = A[M,K] @ W[K,N] + bias[N]
// 128x128 tile, BK=16, 256 thr (8 warps 2x4), warp tile 64x32.
// Register-staged pipeline: tile kt+1 gmem loads issue under tile kt MMAs.
// ---------------------------------------------------------------------------
__global__ __launch_bounds__(256) void gemm_bf16x3_kernel(
    const float* __restrict__ A, const float* __restrict__ W,
    const float* __restrict__ bias, float* __restrict__ C,
    int M, int N, int K)
{
    __shared__ uint32_t Ah[128 * SMB], Al[128 * SMB];
    __shared__ uint32_t Bh[128 * SMB], Bl[128 * SMB];

    const int tid  = threadIdx.x;
    const int warp = tid >> 5;
    const int lane = tid & 31;
    const int gid  = lane >> 2;
    const int tig  = lane & 3;
    const int warp_m = (warp & 1) * 64;
    const int warp_n = (warp >> 1) * 32;
    const int mBase = blockIdx.y * 128;
    const int nBase = blockIdx.x * 128;

    // Per-thread loader coordinates (invariant across kt)
    const int aM0 = tid >> 3;             // +32 per slot
    const int aK  = (tid & 7) << 1;
    const int wN  = tid & 127;
    const int wK0 = (tid >> 7) << 1;      // +4 per slot
    const bool wOk = (nBase + wN) < N;

    float2 aPre[4];
    float  wPre[8];

    float acc[4][4][4];
#pragma unroll
    for (int mf = 0; mf < 4; mf++)
#pragma unroll
        for (int nf = 0; nf < 4; nf++)
#pragma unroll
            for (int r = 0; r < 4; r++) acc[mf][nf][r] = 0.f;

    // Prologue: load tile 0
#pragma unroll
    for (int t = 0; t < 4; t++)
        aPre[t] = *(const float2*)(A + (size_t)(mBase + aM0 + t * 32) * K + aK);
#pragma unroll
    for (int t = 0; t < 4; t++) {
        int kk = wK0 + t * 4;
        wPre[t * 2]     = wOk ? W[(size_t)kk       * N + nBase + wN] : 0.f;
        wPre[t * 2 + 1] = wOk ? W[(size_t)(kk + 1) * N + nBase + wN] : 0.f;
    }

    const int nkt = K >> 4;
    for (int kt = 0; kt < nkt; kt++) {
        // Split + store staged tile
#pragma unroll
        for (int t = 0; t < 4; t++) {
            uint32_t hi, lo;
            split2(aPre[t].x, aPre[t].y, hi, lo);
            int m = aM0 + t * 32;
            Ah[m * SMB + (aK >> 1)] = hi;
            Al[m * SMB + (aK >> 1)] = lo;
        }
#pragma unroll
        for (int t = 0; t < 4; t++) {
            uint32_t hi, lo;
            split2(wPre[t * 2], wPre[t * 2 + 1], hi, lo);
            int kk = wK0 + t * 4;
            Bh[wN * SMB + (kk >> 1)] = hi;
            Bl[wN * SMB + (kk >> 1)] = lo;
        }
        __syncthreads();

        // Prefetch next tile (completes under the MMAs below)
        if (kt + 1 < nkt) {
            const int kOff = (kt + 1) << 4;
#pragma unroll
            for (int t = 0; t < 4; t++)
                aPre[t] = *(const float2*)(A + (size_t)(mBase + aM0 + t * 32) * K + kOff + aK);
#pragma unroll
            for (int t = 0; t < 4; t++) {
                int kk = kOff + wK0 + t * 4;
                wPre[t * 2]     = wOk ? W[(size_t)kk       * N + nBase + wN] : 0.f;
                wPre[t * 2 + 1] = wOk ? W[(size_t)(kk + 1) * N + nBase + wN] : 0.f;
            }
        }

        uint32_t ah[4][4], al[4][4];
#pragma unroll
        for (int mf = 0; mf < 4; mf++) {
            int m0 = (warp_m + (mf << 4) + gid) * SMB + tig;
            ah[mf][0] = Ah[m0];
            ah[mf][1] = Ah[m0 + 8 * SMB];
            ah[mf][2] = Ah[m0 + 4];
            ah[mf][3] = Ah[m0 + 8 * SMB + 4];
            al[mf][0] = Al[m0];
            al[mf][1] = Al[m0 + 8 * SMB];
            al[mf][2] = Al[m0 + 4];
            al[mf][3] = Al[m0 + 8 * SMB + 4];
        }
#pragma unroll
        for (int nf = 0; nf < 4; nf++) {
            int n0 = (warp_n + (nf << 3) + gid) * SMB + tig;
            uint32_t bh0 = Bh[n0], bh1 = Bh[n0 + 4];
            uint32_t bl0 = Bl[n0], bl1 = Bl[n0 + 4];
#pragma unroll
            for (int mf = 0; mf < 4; mf++) {
                MMA_BF16(acc[mf][nf], ah[mf], bh0, bh1);
                MMA_BF16(acc[mf][nf], ah[mf], bl0, bl1);
                MMA_BF16(acc[mf][nf], al[mf], bh0, bh1);
            }
        }
        __syncthreads();
    }

#pragma unroll
    for (int mf = 0; mf < 4; mf++) {
#pragma unroll
        for (int nf = 0; nf < 4; nf++) {
            int row0 = mBase + warp_m + (mf << 4) + gid;
            int col0 = nBase + warp_n + (nf << 3) + (tig << 1);
            if (col0 < N) {
                float b0 = bias[col0], b1 = bias[col0 + 1];
                C[(size_t)row0 * N + col0]           = acc[mf][nf][0] + b0;
                C[(size_t)row0 * N + col0 + 1]       = acc[mf][nf][1] + b1;
                C[(size_t)(row0 + 8) * N + col0]     = acc[mf][nf][2] + b0;
                C[(size_t)(row0 + 8) * N + col0 + 1] = acc[mf][nf][3] + b1;
            }
        }
    }
}

// ---------------------------------------------------------------------------
// SiLU gate
// ---------------------------------------------------------------------------
__global__ void gate_kernel(const float* __restrict__ vp, float* __restrict__ vg)
{
    int idx = blockIdx.x * blockDim.x + threadIdx.x;
    if (idx >= BS * DVH) return;
    int m = idx / DVH, j = idx - m * DVH;
    float a = vp[(size_t)m * NV + j];
    float g = vp[(size_t)m * NV + DVH + j];
    vg[idx] = a * (g / (1.f + __expf(-g)));
}

// ---------------------------------------------------------------------------
// RoPE in place on [BS, H, 128]; pairs (d, d+64).
// ---------------------------------------------------------------------------
__global__ void rope_kernel(float* __restrict__ x)
{
    int idx = blockIdx.x * blockDim.x + threadIdx.x;
    if (idx >= BS * Hh * 64) return;
    int d  = idx & 63;
    int h  = (idx >> 6) & 15;
    int bs = idx >> 10;
    int s  = bs & (Sq - 1);
    float invf = powf(10000.f, -(float)d * (1.f / 64.f));
    float ang  = (float)s * invf;
    float c, sn;
    sincosf(ang, &sn, &c);
    size_t base = (size_t)bs * DM + (size_t)h * DQKd + d;
    float x1 = x[base], x2 = x[base + 64];
    x[base]      = x1 * c - x2 * sn;
    x[base + 64] = x2 * c + x1 * sn;
}

// ---------------------------------------------------------------------------
// Scores via 3xBF16: sc[z,i,j] = SCALE * sum_d Q[z,i,d] K[z,j,d]
// Both operands k-contiguous (stride DM). Register-staged pipeline.
// ---------------------------------------------------------------------------
__global__ __launch_bounds__(256) void score_bf16x3_kernel(
    const float* __restrict__ qp, const float* __restrict__ kp,
    float* __restrict__ sc)
{
    const int iBase = blockIdx.y * 128;
    const int jBase = blockIdx.x * 128;
    if (jBase > iBase + 127) return;
    const int z = blockIdx.z;
    const int b = z >> 4, h = z & 15;
    const size_t hbase = ((size_t)b * Sq) * DM + (size_t)h * DQKd;
    const float* Q  = qp + hbase;
    const float* Km = kp + hbase;

    __shared__ uint32_t Ah[128 * SMB], Al[128 * SMB];
    __shared__ uint32_t Bh[128 * SMB], Bl[128 * SMB];

    const int tid  = threadIdx.x;
    const int warp = tid >> 5;
    const int lane = tid & 31;
    const int gid  = lane >> 2;
    const int tig  = lane & 3;
    const int warp_m = (warp & 1) * 64;
    const int warp_n = (warp >> 1) * 32;

    const int aM0 = tid >> 3;
    const int aK  = (tid & 7) << 1;

    float2 qPre[4], kPre[4];

    float acc[4][4][4];
#pragma unroll
    for (int mf = 0; mf < 4; mf++)
#pragma unroll
        for (int nf = 0; nf < 4; nf++)
#pragma unroll
            for (int r = 0; r < 4; r++) acc[mf][nf][r] = 0.f;

#pragma unroll
    for (int t = 0; t < 4; t++) {
        qPre[t] = *(const float2*)(Q  + (size_t)(iBase + aM0 + t * 32) * DM + aK);
        kPre[t] = *(const float2*)(Km + (size_t)(jBase + aM0 + t * 32) * DM + aK);
    }

    for (int kt = 0; kt < 8; kt++) {    // DQK / 16
#pragma unroll
        for (int t = 0; t < 4; t++) {
            uint32_t hi, lo;
            split2(qPre[t].x, qPre[t].y, hi, lo);
            int m = aM0 + t * 32;
            Ah[m * SMB + (aK >> 1)] = hi;
            Al[m * SMB + (aK >> 1)] = lo;
            split2(kPre[t].x, kPre[t].y, hi, lo);
            Bh[m * SMB + (aK >> 1)] = hi;
            Bl[m * SMB + (aK >> 1)] = lo;
        }
        __syncthreads();

        if (kt + 1 < 8) {
            const int kOff = (kt + 1) << 4;
#pragma unroll
            for (int t = 0; t < 4; t++) {
                qPre[t] = *(const float2*)(Q  + (size_t)(iBase + aM0 + t * 32) * DM + kOff + aK);
                kPre[t] = *(const float2*)(Km + (size_t)(jBase + aM0 + t * 32) * DM + kOff + aK);
            }
        }

        uint32_t ah[4][4], al[4][4];
#pragma unroll
        for (int mf = 0; mf < 4; mf++) {
            int m0 = (warp_m + (mf << 4) + gid) * SMB + tig;
            ah[mf][0] = Ah[m0];
            ah[mf][1] = Ah[m0 + 8 * SMB];
            ah[mf][2] = Ah[m0 + 4];
            ah[mf][3] = Ah[m0 + 8 * SMB + 4];
            al[mf][0] = Al[m0];
            al[mf][1] = Al[m0 + 8 * SMB];
            al[mf][2] = Al[m0 + 4];
            al[mf][3] = Al[m0 + 8 * SMB + 4];
        }
#pragma unroll
        for (int nf = 0; nf < 4; nf++) {
            int n0 = (warp_n + (nf << 3) + gid) * SMB + tig;
            uint32_t bh0 = Bh[n0], bh1 = Bh[n0 + 4];
            uint32_t bl0 = Bl[n0], bl1 = Bl[n0 + 4];
#pragma unroll
            for (int mf = 0; mf < 4; mf++) {
                MMA_BF16(acc[mf][nf], ah[mf], bh0, bh1);
                MMA_BF16(acc[mf][nf], ah[mf], bl0, bl1);
                MMA_BF16(acc[mf][nf], al[mf], bh0, bh1);
            }
        }
        __syncthreads();
    }

#pragma unroll
    for (int mf = 0; mf < 4; mf++) {
#pragma unroll
        for (int nf = 0; nf < 4; nf++) {
            int row0 = iBase + warp_m + (mf << 4) + gid;
            int col0 = jBase + warp_n + (nf << 3) + (tig << 1);
            size_t r0 = ((size_t)z * Sq + row0) * Sq;
            size_t r1 = ((size_t)z * Sq + row0 + 8) * Sq;
            sc[r0 + col0]     = acc[mf][nf][0] * ATT_SCALE;
            sc[r0 + col0 + 1] = acc[mf][nf][1] * ATT_SCALE;
            sc[r1 + col0]     = acc[mf][nf][2] * ATT_SCALE;
            sc[r1 + col0 + 1] = acc[mf][nf][3] * ATT_SCALE;
        }
    }
}

// ---------------------------------------------------------------------------
// Causal softmax, row cached in smem. Zero-fills (i, next 128 boundary].
// ---------------------------------------------------------------------------
__global__ __launch_bounds__(256) void softmax_kernel(float* __restrict__ sc)
{
    __shared__ float rows[2048];
    __shared__ float red[8];
    const int gid = blockIdx.x;          // z*Sq + i
    const int i   = gid & (Sq - 1);
    float* row = sc + (size_t)gid * Sq;
    const int L   = i + 1;
    const int tid = threadIdx.x;

    float m = -1e30f;
    for (int j = tid; j < L; j += 256) {
        float v = row[j];
        rows[j] = v;
        m = fmaxf(m, v);
    }
#pragma unroll
    for (int o = 16; o; o >>= 1) m = fmaxf(m, __shfl_xor_sync(~0u, m, o));
    if ((tid & 31) == 0) red[tid >> 5] = m;
    __syncthreads();
    m = red[0];
#pragma unroll
    for (int w = 1; w < 8; w++) m = fmaxf(m, red[w]);
    __syncthreads();

    float sum = 0.f;
    for (int j = tid; j < L; j += 256) {
        float e = __expf(rows[j] - m);
        rows[j] = e;
        sum += e;
    }
#pragma unroll
    for (int o = 16; o; o >>= 1) sum += __shfl_xor_sync(~0u, sum, o);
    if ((tid & 31) == 0) red[tid >> 5] = sum;
    __syncthreads();
    sum = 0.f;
#pragma unroll
    for (int w = 0; w < 8; w++) sum += red[w];
    float inv = 1.f / sum;

    for (int j = tid; j < L; j += 256) row[j] = rows[j] * inv;
    const int bound = ((i >> 7) + 1) << 7;
    for (int j = L + tid; j < bound; j += 256) row[j] = 0.f;
}

// ---------------------------------------------------------------------------
// O = P @ V via 3xBF16, per (b,h). Block 128 x 96 (DV=85 padded), BK=16.
// Warp tile 64x24. Causal k-limit iBase+128. Register-staged pipeline.
// ---------------------------------------------------------------------------
__global__ __launch_bounds__(256) void pv_bf16x3_kernel(
    const float* __restrict__ sc, const float* __restrict__ vg,
    float* __restrict__ oc)
{
    const int z = blockIdx.z;
    const int b = z >> 4, h = z & 15;
    const int iBase = blockIdx.y * 128;

    __shared__ uint32_t Ph[128 * SMB], Pl[128 * SMB];
    __shared__ uint32_t Vhs[96 * SMB], Vls[96 * SMB];

    const int tid  = threadIdx.x;
    const int warp = tid >> 5;
    const int lane = tid & 31;
    const int gid  = lane >> 2;
    const int tig  = lane & 3;
    const int warp_m = (warp & 1) * 64;
    const int warp_n = (warp >> 1) * 24;

    const int aM0 = tid >> 3;
    const int aK  = (tid & 7) << 1;

    float acc[4][3][4];
#pragma unroll
    for (int mf = 0; mf < 4; mf++)
#pragma unroll
        for (int nf = 0; nf < 3; nf++)
#pragma unroll
            for (int r = 0; r < 4; r++) acc[mf][nf][r] = 0.f;

    const int nj = iBase + 128;
    const size_t zrow = (size_t)z * Sq;
    const float* Vg = vg + (size_t)h * DVd;

    float2 pPre[4];
    float  vPre[6];

    // Prologue jt = 0
#pragma unroll
    for (int t = 0; t < 4; t++)
        pPre[t] = *(const float2*)(sc + (zrow + iBase + aM0 + t * 32) * Sq + aK);
#pragma unroll
    for (int t = 0; t < 3; t++) {
        int p = tid + (t << 8);
        int n  = p % 96;
        int kk = (p / 96) << 1;
        float v0 = 0.f, v1 = 0.f;
        if (n < DVd) {
            size_t base = ((size_t)(b * Sq + kk)) * DVH + n;
            v0 = Vg[base];
            v1 = Vg[base + DVH];
        }
        vPre[t * 2] = v0; vPre[t * 2 + 1] = v1;
    }

    for (int jt = 0; jt < nj; jt += 16) {
#pragma unroll
        for (int t = 0; t < 4; t++) {
            uint32_t hi, lo;
            split2(pPre[t].x, pPre[t].y, hi, lo);
            int m = aM0 + t * 32;
            Ph[m * SMB + (aK >> 1)] = hi;
            Pl[m * SMB + (aK >> 1)] = lo;
        }
#pragma unroll
        for (int t = 0; t < 3; t++) {
            int p = tid + (t << 8);
            int n  = p % 96;
            int kk = (p / 96) << 1;
            uint32_t hi, lo;
            split2(vPre[t * 2], vPre[t * 2 + 1], hi, lo);
            Vhs[n * SMB + (kk >> 1)] = hi;
            Vls[n * SMB + (kk >> 1)] = lo;
        }
        __syncthreads();

        if (jt + 16 < nj) {
            const int jn = jt + 16;
#pragma unroll
            for (int t = 0; t < 4; t++)
                pPre[t] = *(const float2*)(sc + (zrow + iBase + aM0 + t * 32) * Sq + jn + aK);
#pragma unroll
            for (int t = 0; t < 3; t++) {
                int p = tid + (t << 8);
                int n  = p % 96;
                int kk = (p / 96) << 1;
                float v0 = 0.f, v1 = 0.f;
                if (n < DVd) {
                    size_t base = ((size_t)(b * Sq + jn + kk)) * DVH + n;
                    v0 = Vg[base];
                    v1 = Vg[base + DVH];
                }
                vPre[t * 2] = v0; vPre[t * 2 + 1] = v1;
            }
        }

        uint32_t ah[4][4], al[4][4];
#pragma unroll
        for (int mf = 0; mf < 4; mf++) {
            int m0 = (warp_m + (mf << 4) + gid) * SMB + tig;
            ah[mf][0] = Ph[m0];
            ah[mf][1] = Ph[m0 + 8 * SMB];
            ah[mf][2] = Ph[m0 + 4];
            ah[mf][3] = Ph[m0 + 8 * SMB + 4];
            al[mf][0] = Pl[m0];
            al[mf][1] = Pl[m0 + 8 * SMB];
            al[mf][2] = Pl[m0 + 4];
            al[mf][3] = Pl[m0 + 8 * SMB + 4];
        }
#pragma unroll
        for (int nf = 0; nf < 3; nf++) {
            int n0 = (warp_n + (nf << 3) + gid) * SMB + tig;
            uint32_t bh0 = Vhs[n0], bh1 = Vhs[n0 + 4];
            uint32_t bl0 = Vls[n0], bl1 = Vls[n0 + 4];
#pragma unroll
            for (int mf = 0; mf < 4; mf++) {
                MMA_BF16(acc[mf][nf], ah[mf], bh0, bh1);
                MMA_BF16(acc[mf][nf], ah[mf], bl0, bl1);
                MMA_BF16(acc[mf][nf], al[mf], bh0, bh1);
            }
        }
        __syncthreads();
    }

    float* Oh = oc + (size_t)h * DVd;
#pragma unroll
    for (int mf = 0; mf < 4; mf++) {
#pragma unroll
        for (int nf = 0; nf < 3; nf++) {
            int row0 = iBase + warp_m + (mf << 4) + gid;
            int col0 = warp_n + (nf << 3) + (tig << 1);
            size_t r0 = ((size_t)(b * Sq + row0)) * DVH;
            size_t r1 = ((size_t)(b * Sq + row0 + 8)) * DVH;
            if (col0 < DVd) {
                Oh[r0 + col0] = acc[mf][nf][0];
                Oh[r1 + col0] = acc[mf][nf][2];
            }
            if (col0 + 1 < DVd) {
                Oh[r0 + col0 + 1] = acc[mf][nf][1];
                Oh[r1 + col0 + 1] = acc[mf][nf][3];
            }
        }
    }
}

// ---------------------------------------------------------------------------
// Launch
// Inputs: 0:q 1:k 2:v 3:mask(unused) 4:Wq 5:bq 6:Wk 7:bk 8:Wv 9:bv 10:Wo 11:bo
// ---------------------------------------------------------------------------
extern "C" void kernel_launch(void* const* d_in, const int* in_sizes, int n_in,
                              void* d_out, int out_size)
{
    const float* q  = (const float*)d_in[0];
    const float* k  = (const float*)d_in[1];
    const float* v  = (const float*)d_in[2];
    const float* Wq = (const float*)d_in[4];
    const float* bq = (const float*)d_in[5];
    const float* Wk = (const float*)d_in[6];
    const float* bk = (const float*)d_in[7];
    const float* Wv = (const float*)d_in[8];
    const float* bv = (const float*)d_in[9];
    const float* Wo = (const float*)d_in[10];
    const float* bo = (const float*)d_in[11];
    float* out = (float*)d_out;

    float *qp, *kp, *vp, *vg, *oc, *sc;
    cudaGetSymbolAddress((void**)&qp, g_qp);
    cudaGetSymbolAddress((void**)&kp, g_kp);
    cudaGetSymbolAddress((void**)&vp, g_vp);
    cudaGetSymbolAddress((void**)&vg, g_vg);
    cudaGetSymbolAddress((void**)&oc, g_oc);
    cudaGetSymbolAddress((void**)&sc, g_sc);

    // Projections (3xBF16 tensor cores, split-on-store, pipelined)
    gemm_bf16x3_kernel<<<dim3(16, 32), 256>>>(q, Wq, bq, qp, BS, DM, DM);
    gemm_bf16x3_kernel<<<dim3(16, 32), 256>>>(k, Wk, bk, kp, BS, DM, DM);
    gemm_bf16x3_kernel<<<dim3(22, 32), 256>>>(v, Wv, bv, vp, BS, NV, DM);

    // SiLU gate on V
    gate_kernel<<<(BS * DVH + 255) / 256, 256>>>(vp, vg);

    // RoPE on Q and K (in place)
    rope_kernel<<<(BS * Hh * 64 + 255) / 256, 256>>>(qp);
    rope_kernel<<<(BS * Hh * 64 + 255) / 256, 256>>>(kp);

    // Attention
    score_bf16x3_kernel<<<dim3(16, 16, 32), 256>>>(qp, kp, sc);
    softmax_kernel<<<Bsz * Hh * Sq, 256>>>(sc);
    pv_bf16x3_kernel<<<dim3(1, Sq / 128, Bsz * Hh), 256>>>(sc, vg, oc);

    // Output projection
    gemm_bf16x3_kernel<<<dim3(16, 32), 256>>>(oc, Wo, bo, out, BS, DM, DVH);
}